// round 12
// baseline (speedup 1.0000x reference)
#include <cuda_runtime.h>
#include <cuda_bf16.h>
#include <cstdint>

// out[b,p,l] = w_in[p, x[b,l]];  B=64, L=4096, P=128, VOCAB=32000, fp32.
#define PB   128
#define VOC  32000
#define BB   64
#define LL   4096
#define TOK  32            // tokens per gather tile
#define NTILES ((LL / TOK) * BB)   // 8192
#define GRID_PERSIST 2048          // 8192/2048 = exactly 4 iters per block
#define PITCH_B 528        // smem row pitch: 512 B + 16 B pad = 33 float4 (odd)
#define PITCH_F4 33

// Transposed weight table w_t[v][p] (16.38 MB, mostly L2-resident).
__device__ __align__(512) float g_wt[(size_t)VOC * PB];

// ---------------- PTX helpers ----------------
__device__ __forceinline__ uint32_t smem_u32(const void* p) {
    return (uint32_t)__cvta_generic_to_shared(p);
}
__device__ __forceinline__ void mbar_init(uint32_t mbar, uint32_t cnt) {
    asm volatile("mbarrier.init.shared.b64 [%0], %1;" :: "r"(mbar), "r"(cnt) : "memory");
}
__device__ __forceinline__ void mbar_expect_tx(uint32_t mbar, uint32_t bytes) {
    asm volatile("mbarrier.arrive.expect_tx.shared.b64 _, [%0], %1;"
                 :: "r"(mbar), "r"(bytes) : "memory");
}
__device__ __forceinline__ void mbar_wait(uint32_t mbar, uint32_t parity) {
    asm volatile(
        "{\n\t"
        ".reg .pred P1;\n\t"
        "WAIT_LOOP_%=:\n\t"
        "mbarrier.try_wait.parity.acquire.cta.shared::cta.b64 P1, [%0], %1, 0x989680;\n\t"
        "@P1 bra.uni WAIT_DONE_%=;\n\t"
        "bra.uni WAIT_LOOP_%=;\n\t"
        "WAIT_DONE_%=:\n\t"
        "}"
        :: "r"(mbar), "r"(parity) : "memory");
}
__device__ __forceinline__ void bulk_g2s(uint32_t dst_smem, const void* src_gmem,
                                         uint32_t bytes, uint32_t mbar) {
    asm volatile(
        "cp.async.bulk.shared::cluster.global.mbarrier::complete_tx::bytes "
        "[%0], [%1], %2, [%3];"
        :: "r"(dst_smem), "l"(src_gmem), "r"(bytes), "r"(mbar) : "memory");
}

// ---------------------------------------------------------------------------
// Kernel A: transpose w_in(P, VOC) -> g_wt(VOC, P).  Zero smem, zero sync.
// Grid (250, 4): block covers 128 v x 32 p. Warp w owns p-quad p0 = by*32+4w;
// lane owns v-quad v0 + 4*lane. 4x coalesced LDG.128 reads, 4x4 register
// transpose, 4x STG.128 16 B-scatter writes (sector halves merged in L2 by
// the neighbor warp of the same block).
// ---------------------------------------------------------------------------
__global__ __launch_bounds__(256) void transpose_kernel(const float* __restrict__ w_in) {
    const int lane = threadIdx.x & 31;
    const int wrp  = threadIdx.x >> 5;           // 0..7
    const int v0   = blockIdx.x * 128;
    const int p0   = blockIdx.y * 32 + 4 * wrp;
    const int v    = v0 + 4 * lane;

    const size_t base = (size_t)p0 * VOC + v;
    const float4 a0 = *reinterpret_cast<const float4*>(&w_in[base]);
    const float4 a1 = *reinterpret_cast<const float4*>(&w_in[base + (size_t)VOC]);
    const float4 a2 = *reinterpret_cast<const float4*>(&w_in[base + 2 * (size_t)VOC]);
    const float4 a3 = *reinterpret_cast<const float4*>(&w_in[base + 3 * (size_t)VOC]);

    float4* __restrict__ dst = reinterpret_cast<float4*>(&g_wt[(size_t)v * PB + p0]);
    const size_t rs = PB / 4;                    // f4 stride between v-rows
    dst[0]      = make_float4(a0.x, a1.x, a2.x, a3.x);   // v
    dst[rs]     = make_float4(a0.y, a1.y, a2.y, a3.y);   // v+1
    dst[2 * rs] = make_float4(a0.z, a1.z, a2.z, a3.z);   // v+2
    dst[3 * rs] = make_float4(a0.w, a1.w, a2.w, a3.w);   // v+3
}

// ---------------------------------------------------------------------------
// Kernel B: PERSISTENT gather. Grid = 2048 blocks x 128 threads; each block
// handles exactly 4 (b, l0) tiles (8192/2048), re-arming the same two
// mbarriers each iteration (parity = iter & 1). Amortizes per-block startup
// and removes the partial-wave tail of the 8192-block launch.
// Per tile (identical to R7 hot path):
//   Warp 0: lane 0 re-arms both barriers (expect_tx 8 KB each), __syncwarp,
//     then lane t<32 TMA-fetches g_wt[x[b][l0+t]] (512 B) into smem row
//     R(t) = 2g + (j&1) + 16*(j>>1)  (g=t>>2, j=t&3).
//   All warps, half h: block-uniform mbar wait, 4x conflict-free LDS.128,
//     4x4 register transpose, 4x STG.128 (__stcs) — 64 B-contiguous runs.
//   __syncthreads before next iteration reuses the buffer.
// ---------------------------------------------------------------------------
__global__ __launch_bounds__(128) void gather_kernel(
    const int* __restrict__ x, float* __restrict__ out) {
    __shared__ __align__(16) float tile[TOK * PITCH_F4 * 4];
    __shared__ __align__(8) unsigned long long mbar_storage[2];
    const float4* s4 = reinterpret_cast<const float4*>(tile);
    const uint32_t mbar0 = smem_u32(&mbar_storage[0]);
    const uint32_t mbar1 = smem_u32(&mbar_storage[1]);

    const int tid  = threadIdx.x;
    const int lane = tid & 31;
    const int wrp  = tid >> 5;

    if (tid == 0) { mbar_init(mbar0, 1); mbar_init(mbar1, 1); }
    __syncthreads();

    const int gl = lane & 3;                     // token-group within half
    const int q  = wrp * 8 + (lane >> 2);        // p-quad 0..31
    float4* __restrict__ out4 = reinterpret_cast<float4*>(out);
    const size_t rstride = LL / 4;               // float4s per p-row

    // TMA smem row for warp 0 (token = lane): R = 2g + (j&1) + 16*(j>>1).
    const int Rr = 2 * (lane >> 2) + (lane & 1) + 16 * ((lane & 3) >> 1);

    #pragma unroll 1
    for (int it = 0; it < NTILES / GRID_PERSIST; it++) {
        const int ti = blockIdx.x + it * GRID_PERSIST;
        const int b  = ti >> 7;                  // LL/TOK = 128 tiles per batch
        const int l0 = (ti & 127) * TOK;
        const int par = it & 1;

        if (wrp == 0) {
            if (lane == 0) {
                mbar_expect_tx(mbar0, 16 * 512);
                mbar_expect_tx(mbar1, 16 * 512);
            }
            __syncwarp();
            const int v = x[(size_t)b * LL + l0 + lane];
            bulk_g2s(smem_u32(tile) + Rr * PITCH_B, &g_wt[(size_t)v * PB], 512,
                     lane < 16 ? mbar0 : mbar1);
        }

        #pragma unroll
        for (int h = 0; h < 2; h++) {
            mbar_wait(h == 0 ? mbar0 : mbar1, par);
            const int g = h * 4 + gl;            // token group (tokens 4g..4g+3)
            const int r0 = 2 * g;
            float4 f0 = s4[(r0 + 0)  * PITCH_F4 + q];   // j=0
            float4 f1 = s4[(r0 + 1)  * PITCH_F4 + q];   // j=1
            float4 f2 = s4[(r0 + 16) * PITCH_F4 + q];   // j=2
            float4 f3 = s4[(r0 + 17) * PITCH_F4 + q];   // j=3
            // Transpose: oj = tokens {4g..4g+3} at p = 4q+j.
            float4 o0 = make_float4(f0.x, f1.x, f2.x, f3.x);
            float4 o1 = make_float4(f0.y, f1.y, f2.y, f3.y);
            float4 o2 = make_float4(f0.z, f1.z, f2.z, f3.z);
            float4 o3 = make_float4(f0.w, f1.w, f2.w, f3.w);
            const size_t obase = ((size_t)b * PB + 4 * q) * rstride + (l0 >> 2) + g;
            __stcs(&out4[obase],               o0);
            __stcs(&out4[obase + rstride],     o1);
            __stcs(&out4[obase + 2 * rstride], o2);
            __stcs(&out4[obase + 3 * rstride], o3);
        }

        __syncthreads();                         // smem reuse fence for next iter
    }
}

// ---------------------------------------------------------------------------
// Launch: plain serial launches (PDL regressed — R8 post-mortem).
// ---------------------------------------------------------------------------
extern "C" void kernel_launch(void* const* d_in, const int* in_sizes, int n_in,
                              void* d_out, int out_size) {
    const int*   x    = (const int*)d_in[0];     // (64, 4096) int32
    const float* w_in = (const float*)d_in[1];   // (128, 32000) fp32
    float*       out  = (float*)d_out;           // (64, 128, 4096) fp32
    (void)in_sizes; (void)n_in; (void)out_size;

    transpose_kernel<<<dim3(VOC / 128, 4), 256>>>(w_in);
    gather_kernel<<<GRID_PERSIST, 128>>>(x, out);
}

// round 13
// speedup vs baseline: 1.1413x; 1.1413x over previous
#include <cuda_runtime.h>
#include <cuda_bf16.h>
#include <cstdint>

// out[b,p,l] = w_in[p, x[b,l]];  B=64, L=4096, P=128, VOCAB=32000, fp32.
#define PB   128
#define VOC  32000
#define BB   64
#define LL   4096
#define TOK  32            // tokens per gather block
#define PITCH_B 528        // smem row pitch: 512 B + 16 B pad = 33 float4 (odd)
#define PITCH_F4 33

// Transposed weight table w_t[v][p] (16.38 MB, mostly L2-resident).
__device__ __align__(512) float g_wt[(size_t)VOC * PB];

// ---------------- PTX helpers ----------------
__device__ __forceinline__ uint32_t smem_u32(const void* p) {
    return (uint32_t)__cvta_generic_to_shared(p);
}
__device__ __forceinline__ void mbar_init(uint32_t mbar, uint32_t cnt) {
    asm volatile("mbarrier.init.shared.b64 [%0], %1;" :: "r"(mbar), "r"(cnt) : "memory");
}
__device__ __forceinline__ void mbar_expect_tx(uint32_t mbar, uint32_t bytes) {
    asm volatile("mbarrier.arrive.expect_tx.shared.b64 _, [%0], %1;"
                 :: "r"(mbar), "r"(bytes) : "memory");
}
__device__ __forceinline__ void mbar_wait(uint32_t mbar, uint32_t parity) {
    asm volatile(
        "{\n\t"
        ".reg .pred P1;\n\t"
        "WAIT_LOOP_%=:\n\t"
        "mbarrier.try_wait.parity.acquire.cta.shared::cta.b64 P1, [%0], %1, 0x989680;\n\t"
        "@P1 bra.uni WAIT_DONE_%=;\n\t"
        "bra.uni WAIT_LOOP_%=;\n\t"
        "WAIT_DONE_%=:\n\t"
        "}"
        :: "r"(mbar), "r"(parity) : "memory");
}
__device__ __forceinline__ void bulk_g2s(uint32_t dst_smem, const void* src_gmem,
                                         uint32_t bytes, uint32_t mbar) {
    asm volatile(
        "cp.async.bulk.shared::cluster.global.mbarrier::complete_tx::bytes "
        "[%0], [%1], %2, [%3];"
        :: "r"(dst_smem), "l"(src_gmem), "r"(bytes), "r"(mbar) : "memory");
}

// ---------------------------------------------------------------------------
// Kernel A: transpose w_in(P, VOC) -> g_wt(VOC, P).  Zero smem, zero sync.
// Grid (250, 4), block 256 threads covering 128 v x 32 p.
// Warp tiling (wavefront-optimized): warp = 32 v x 16 p.
//   wv = w & 3 (v-tile of 32), wp = w >> 2 (p-tile of 16).
//   lane = h + 4*g: h in [0,4) = p-quad, g in [0,8) = v-quad.
// Reads (k=0..3): LDG.128 w_in[p_base+4h+k][v_base+4g] — 8 same-h lanes form
//   one 128 B line, 4 h-rows -> 4 lines/instr (fully coalesced).
// Writes (j=0..3): STG.128 g_wt[v_base+4g+j][p_base+4h] — lanes h=0..3 write
//   64 B contiguous in ONE line (s=4): 8 lines/instr vs 32 in the s=1 layout.
// Total 48 L1 wavefronts per warp per 2 KB (vs 144) -> ~3x less L1 work.
// ---------------------------------------------------------------------------
__global__ __launch_bounds__(256) void transpose_kernel(const float* __restrict__ w_in) {
    const int lane = threadIdx.x & 31;
    const int w    = threadIdx.x >> 5;           // 0..7
    const int wv   = w & 3;                      // v-tile (32 v each)
    const int wp   = w >> 2;                     // p-tile (16 p each)
    const int h    = lane & 3;                   // p-quad within warp
    const int g    = lane >> 2;                  // v-quad within warp

    const int v_base = blockIdx.x * 128 + 32 * wv + 4 * g;
    const int p_base = blockIdx.y * 32 + 16 * wp + 4 * h;

    const size_t rbase = (size_t)p_base * VOC + v_base;
    const float4 a0 = *reinterpret_cast<const float4*>(&w_in[rbase]);
    const float4 a1 = *reinterpret_cast<const float4*>(&w_in[rbase + (size_t)VOC]);
    const float4 a2 = *reinterpret_cast<const float4*>(&w_in[rbase + 2 * (size_t)VOC]);
    const float4 a3 = *reinterpret_cast<const float4*>(&w_in[rbase + 3 * (size_t)VOC]);

    // o_j = w_in[p_base..p_base+3][v_base+j] = row (v_base+j), cols p_base..+3.
    float4* __restrict__ dst = reinterpret_cast<float4*>(&g_wt[(size_t)v_base * PB + p_base]);
    const size_t rs = PB / 4;                    // f4 stride between v-rows
    dst[0]      = make_float4(a0.x, a1.x, a2.x, a3.x);   // v_base
    dst[rs]     = make_float4(a0.y, a1.y, a2.y, a3.y);   // v_base+1
    dst[2 * rs] = make_float4(a0.z, a1.z, a2.z, a3.z);   // v_base+2
    dst[3 * rs] = make_float4(a0.w, a1.w, a2.w, a3.w);   // v_base+3
}

// ---------------------------------------------------------------------------
// Kernel B: gather (exact R7 structure — best measured: 28.0 us).
// Block: 128 threads, (b = blockIdx.y, 32 tokens).
// Token t (g=t>>2, j=t&3) lands at smem row R = 2g + (j&1) + 16*(j>>1).
// Two mbarriers (tokens 0..15 / 16..31, 8 KB halves), all TMA up front;
// waits are block-uniform at the h-loop (lane-divergent waits regressed, R9).
// Phase 2 half h: thread (g = 4h + (lane&3), q = wrp*8 + (lane>>2)):
//   4x conflict-free LDS.128, 4x4 register transpose, 4x STG.128 (__stcs).
// ---------------------------------------------------------------------------
__global__ __launch_bounds__(128) void gather_kernel(
    const int* __restrict__ x, float* __restrict__ out) {
    __shared__ __align__(16) float tile[TOK * PITCH_F4 * 4];
    __shared__ __align__(8) unsigned long long mbar_storage[2];
    const float4* s4 = reinterpret_cast<const float4*>(tile);
    const uint32_t mbar0 = smem_u32(&mbar_storage[0]);
    const uint32_t mbar1 = smem_u32(&mbar_storage[1]);

    const int tid  = threadIdx.x;
    const int lane = tid & 31;
    const int wrp  = tid >> 5;
    const int b    = blockIdx.y;
    const int l0   = blockIdx.x * TOK;

    if (tid == 0) { mbar_init(mbar0, 1); mbar_init(mbar1, 1); }
    __syncthreads();
    if (tid == 0) {
        mbar_expect_tx(mbar0, 16 * 512);
        mbar_expect_tx(mbar1, 16 * 512);
    }
    if (tid < TOK) {
        const int v = x[(size_t)b * LL + l0 + tid];
        const int g = tid >> 2, j = tid & 3;
        const int R = 2 * g + (j & 1) + 16 * (j >> 1);
        bulk_g2s(smem_u32(tile) + R * PITCH_B, &g_wt[(size_t)v * PB], 512,
                 tid < 16 ? mbar0 : mbar1);
    }

    const int gl = lane & 3;                     // token-group within half
    const int q  = wrp * 8 + (lane >> 2);        // p-quad 0..31
    float4* __restrict__ out4 = reinterpret_cast<float4*>(out);
    const size_t rstride = LL / 4;               // float4s per p-row

    #pragma unroll
    for (int h = 0; h < 2; h++) {
        mbar_wait(h == 0 ? mbar0 : mbar1, 0);
        const int g = h * 4 + gl;                // token group (tokens 4g..4g+3)
        const int r0 = 2 * g;
        float4 f0 = s4[(r0 + 0)  * PITCH_F4 + q];   // j=0
        float4 f1 = s4[(r0 + 1)  * PITCH_F4 + q];   // j=1
        float4 f2 = s4[(r0 + 16) * PITCH_F4 + q];   // j=2
        float4 f3 = s4[(r0 + 17) * PITCH_F4 + q];   // j=3
        // Transpose: oj = tokens {4g..4g+3} at p = 4q+j.
        float4 o0 = make_float4(f0.x, f1.x, f2.x, f3.x);
        float4 o1 = make_float4(f0.y, f1.y, f2.y, f3.y);
        float4 o2 = make_float4(f0.z, f1.z, f2.z, f3.z);
        float4 o3 = make_float4(f0.w, f1.w, f2.w, f3.w);
        const size_t obase = ((size_t)b * PB + 4 * q) * rstride + (l0 >> 2) + g;
        __stcs(&out4[obase],               o0);
        __stcs(&out4[obase + rstride],     o1);
        __stcs(&out4[obase + 2 * rstride], o2);
        __stcs(&out4[obase + 3 * rstride], o3);
    }
}

// ---------------------------------------------------------------------------
// Launch: plain serial launches (PDL regressed R8; persistence regressed R12).
// ---------------------------------------------------------------------------
extern "C" void kernel_launch(void* const* d_in, const int* in_sizes, int n_in,
                              void* d_out, int out_size) {
    const int*   x    = (const int*)d_in[0];     // (64, 4096) int32
    const float* w_in = (const float*)d_in[1];   // (128, 32000) fp32
    float*       out  = (float*)d_out;           // (64, 128, 4096) fp32
    (void)in_sizes; (void)n_in; (void)out_size;

    transpose_kernel<<<dim3(VOC / 128, 4), 256>>>(w_in);
    gather_kernel<<<dim3(LL / TOK, BB), 128>>>(x, out);
}

// round 14
// speedup vs baseline: 1.1424x; 1.0010x over previous
#include <cuda_runtime.h>
#include <cuda_bf16.h>
#include <cstdint>

// out[b,p,l] = w_in[p, x[b,l]];  B=64, L=4096, P=128, VOCAB=32000, fp32.
#define PB   128
#define VOC  32000
#define BB   64
#define LL   4096
#define TOK  32            // tokens per gather block
#define PITCH_B 528        // smem row pitch: 512 B + 16 B pad = 33 float4 (odd)
#define PITCH_F4 33

// Transposed weight table w_t[v][p] (16.38 MB, mostly L2-resident).
__device__ __align__(512) float g_wt[(size_t)VOC * PB];

// ---------------- PTX helpers ----------------
__device__ __forceinline__ uint32_t smem_u32(const void* p) {
    return (uint32_t)__cvta_generic_to_shared(p);
}
__device__ __forceinline__ void mbar_init(uint32_t mbar, uint32_t cnt) {
    asm volatile("mbarrier.init.shared.b64 [%0], %1;" :: "r"(mbar), "r"(cnt) : "memory");
}
__device__ __forceinline__ void mbar_expect_tx(uint32_t mbar, uint32_t bytes) {
    asm volatile("mbarrier.arrive.expect_tx.shared.b64 _, [%0], %1;"
                 :: "r"(mbar), "r"(bytes) : "memory");
}
__device__ __forceinline__ void mbar_wait(uint32_t mbar, uint32_t parity) {
    asm volatile(
        "{\n\t"
        ".reg .pred P1;\n\t"
        "WAIT_LOOP_%=:\n\t"
        "mbarrier.try_wait.parity.acquire.cta.shared::cta.b64 P1, [%0], %1, 0x989680;\n\t"
        "@P1 bra.uni WAIT_DONE_%=;\n\t"
        "bra.uni WAIT_LOOP_%=;\n\t"
        "WAIT_DONE_%=:\n\t"
        "}"
        :: "r"(mbar), "r"(parity) : "memory");
}
__device__ __forceinline__ void bulk_g2s(uint32_t dst_smem, const void* src_gmem,
                                         uint32_t bytes, uint32_t mbar) {
    asm volatile(
        "cp.async.bulk.shared::cluster.global.mbarrier::complete_tx::bytes "
        "[%0], [%1], %2, [%3];"
        :: "r"(dst_smem), "l"(src_gmem), "r"(bytes), "r"(mbar) : "memory");
}

// ---------------------------------------------------------------------------
// Kernel A: transpose w_in(P, VOC) -> g_wt(VOC, P).  (R7 version — best.)
// Grid (250, 4): block covers 128 v x 32 p. Warp w owns p-quad p0 = by*32+4w;
// lane owns v-quad v0 + 4*lane. 4x coalesced LDG.128 reads, 4x4 register
// transpose, 4x STG.128 16 B-scatter writes (sector halves merged in L2 by
// the neighbor warp of the same block).
// ---------------------------------------------------------------------------
__global__ __launch_bounds__(256) void transpose_kernel(const float* __restrict__ w_in) {
    const int lane = threadIdx.x & 31;
    const int wrp  = threadIdx.x >> 5;           // 0..7
    const int v0   = blockIdx.x * 128;
    const int p0   = blockIdx.y * 32 + 4 * wrp;
    const int v    = v0 + 4 * lane;

    const size_t base = (size_t)p0 * VOC + v;
    const float4 a0 = *reinterpret_cast<const float4*>(&w_in[base]);
    const float4 a1 = *reinterpret_cast<const float4*>(&w_in[base + (size_t)VOC]);
    const float4 a2 = *reinterpret_cast<const float4*>(&w_in[base + 2 * (size_t)VOC]);
    const float4 a3 = *reinterpret_cast<const float4*>(&w_in[base + 3 * (size_t)VOC]);

    float4* __restrict__ dst = reinterpret_cast<float4*>(&g_wt[(size_t)v * PB + p0]);
    const size_t rs = PB / 4;                    // f4 stride between v-rows
    dst[0]      = make_float4(a0.x, a1.x, a2.x, a3.x);   // v
    dst[rs]     = make_float4(a0.y, a1.y, a2.y, a3.y);   // v+1
    dst[2 * rs] = make_float4(a0.z, a1.z, a2.z, a3.z);   // v+2
    dst[3 * rs] = make_float4(a0.w, a1.w, a2.w, a3.w);   // v+3
}

// ---------------------------------------------------------------------------
// Kernel B: gather with FULL-LINE output stores.
// Block: 128 threads, (b = blockIdx.y, 32 tokens).
// Token t (g=t>>2, j=t&3) lands at smem row R = g + 8*j (bijection).
// Single mbarrier (16 KB expect_tx): every phase-2 instruction needs tokens
// from all four j-planes, so no half-split (and waits stay block-uniform).
// Phase 2, pass = 0,1: thread (g = lane&7, qsub = lane>>3),
//   q = wrp*4 + qsub + 16*pass:
//   LDS.128 f_j = s4[(8j+g)*33 + q] — bank (g+q)%8, conflict-free per phase.
//   4x4 register transpose -> o_j = tokens {4g..4g+3} at p = 4q+j.
//   STG.128 out[b][4q+j][l0+4g]: 8 same-qsub lanes (g=0..7) form a FULL
//   128 B line -> 4 lines/instr, each line written exactly once (was twice).
// ---------------------------------------------------------------------------
__global__ __launch_bounds__(128) void gather_kernel(
    const int* __restrict__ x, float* __restrict__ out) {
    __shared__ __align__(16) float tile[TOK * PITCH_F4 * 4];
    __shared__ __align__(8) unsigned long long mbar_storage;
    const float4* s4 = reinterpret_cast<const float4*>(tile);
    const uint32_t mbar = smem_u32(&mbar_storage);

    const int tid  = threadIdx.x;
    const int lane = tid & 31;
    const int wrp  = tid >> 5;
    const int b    = blockIdx.y;
    const int l0   = blockIdx.x * TOK;

    if (tid == 0) mbar_init(mbar, 1);
    __syncthreads();
    if (tid == 0) mbar_expect_tx(mbar, TOK * 512);
    if (tid < TOK) {
        const int v = x[(size_t)b * LL + l0 + tid];
        const int R = (tid >> 2) + 8 * (tid & 3);    // g + 8j
        bulk_g2s(smem_u32(tile) + R * PITCH_B, &g_wt[(size_t)v * PB], 512, mbar);
    }

    const int g    = lane & 7;                   // token group (tokens 4g..4g+3)
    const int qsub = lane >> 3;                  // 0..3
    float4* __restrict__ out4 = reinterpret_cast<float4*>(out);
    const size_t rstride = LL / 4;               // float4s per p-row

    mbar_wait(mbar, 0);

    #pragma unroll
    for (int pass = 0; pass < 2; pass++) {
        const int q = wrp * 4 + qsub + 16 * pass;    // p-quad 0..31
        float4 f0 = s4[(8 * 0 + g) * PITCH_F4 + q];  // token 4g+0
        float4 f1 = s4[(8 * 1 + g) * PITCH_F4 + q];  // token 4g+1
        float4 f2 = s4[(8 * 2 + g) * PITCH_F4 + q];  // token 4g+2
        float4 f3 = s4[(8 * 3 + g) * PITCH_F4 + q];  // token 4g+3
        // Transpose: oj = tokens {4g..4g+3} at p = 4q+j.
        float4 o0 = make_float4(f0.x, f1.x, f2.x, f3.x);
        float4 o1 = make_float4(f0.y, f1.y, f2.y, f3.y);
        float4 o2 = make_float4(f0.z, f1.z, f2.z, f3.z);
        float4 o3 = make_float4(f0.w, f1.w, f2.w, f3.w);
        const size_t obase = ((size_t)b * PB + 4 * q) * rstride + (l0 >> 2) + g;
        __stcs(&out4[obase],               o0);
        __stcs(&out4[obase + rstride],     o1);
        __stcs(&out4[obase + 2 * rstride], o2);
        __stcs(&out4[obase + 3 * rstride], o3);
    }
}

// ---------------------------------------------------------------------------
// Launch: plain serial launches (PDL regressed R8; persistence regressed R12).
// ---------------------------------------------------------------------------
extern "C" void kernel_launch(void* const* d_in, const int* in_sizes, int n_in,
                              void* d_out, int out_size) {
    const int*   x    = (const int*)d_in[0];     // (64, 4096) int32
    const float* w_in = (const float*)d_in[1];   // (128, 32000) fp32
    float*       out  = (float*)d_out;           // (64, 128, 4096) fp32
    (void)in_sizes; (void)n_in; (void)out_size;

    transpose_kernel<<<dim3(VOC / 128, 4), 256>>>(w_in);
    gather_kernel<<<dim3(LL / TOK, BB), 128>>>(x, out);
}